// round 6
// baseline (speedup 1.0000x reference)
#include <cuda_runtime.h>
#include <cstdint>

// FAVOR causal linear attention — R5: 512 threads, 16-warp split of every phase.
// B=1,H=8,D=64,DV=64,N=2048,M=128. Chunk C=128, grid(16,8)=128 blocks (1 wave).
// Layouts: F[m][d]@68, Xt[n][d]@68, Qt[n][m]@132, Kt[t][m]@132, Vt[v][t]@132
// (80 rows, row64=ones), Ssl[v][m]@132. Regions: A=F->Qt, B=Xt->Vt->Os, C=Kt->Ssl.
// Warp w: wn=(w&7)*16 (row tile), half=w>>3 (k- or v- or t- split).

#define HH     8
#define DD     64
#define DVV    64
#define NSEQ   2048
#define MM     128
#define CHUNK  128
#define NCHUNK 16
#define NT     512
#define SX     68
#define SW     132
#define OFF_B  17408
#define OFF_C  34816
#define SM_U32 51712   // 206848 bytes

__device__ float g_S[HH * NCHUNK * 65 * MM];   // [h][c][v*128+m], v=64 is z
__device__ int   g_flag[HH * NCHUNK];

__device__ __forceinline__ uint32_t f2tf32(float x) {
    uint32_t r;
    asm("cvt.rna.tf32.f32 %0, %1;" : "=r"(r) : "f"(x));
    return r;
}
__device__ __forceinline__ void mma_tf32(float* c, const uint32_t* a, const uint32_t* b) {
    asm volatile(
        "mma.sync.aligned.m16n8k8.row.col.f32.tf32.tf32.f32 "
        "{%0,%1,%2,%3}, {%4,%5,%6,%7}, {%8,%9}, {%0,%1,%2,%3};"
        : "+f"(c[0]), "+f"(c[1]), "+f"(c[2]), "+f"(c[3])
        : "r"(a[0]), "r"(a[1]), "r"(a[2]), "r"(a[3]), "r"(b[0]), "r"(b[1]));
}
__device__ __forceinline__ int ld_acquire(const int* p) {
    int v;
    asm volatile("ld.acquire.gpu.b32 %0, [%1];" : "=r"(v) : "l"(p) : "memory");
    return v;
}
// 16-row x 8-tf32-col fragment via ldmatrix (b16 view). A-frag: r[0..3];
// as two B-frags: {r0,r2} (rows +0..7) and {r1,r3} (rows +8..15).
__device__ __forceinline__ void ldsm4(uint32_t r[4], uint32_t sbase,
                                      int row0, int k0, int stride, int lane) {
    uint32_t addr = sbase +
        (uint32_t)(((row0 + (lane & 7) + (lane & 8)) * stride + k0 + ((lane & 16) >> 2)) * 4);
    asm volatile("ldmatrix.sync.aligned.m8n8.x4.shared.b16 {%0,%1,%2,%3}, [%4];"
                 : "=r"(r[0]), "=r"(r[1]), "=r"(r[2]), "=r"(r[3]) : "r"(addr));
}

// phi tile 16n x 64m (3-term tf32): acc[8][4]
__device__ __forceinline__ void phi_mma16(uint32_t sX, uint32_t sXl, uint32_t sF,
                                          uint32_t sFl, int wn, int half, int lane,
                                          float acc[8][4]) {
    #pragma unroll
    for (int mi = 0; mi < 8; mi++)
        #pragma unroll
        for (int r = 0; r < 4; r++) acc[mi][r] = 0.f;
    #pragma unroll 2
    for (int k0 = 0; k0 < DD; k0 += 8) {
        uint32_t axh[4], axl[4];
        ldsm4(axh, sX,  wn, k0, SX, lane);
        ldsm4(axl, sXl, wn, k0, SX, lane);
        #pragma unroll
        for (int mj = 0; mj < 4; mj++) {
            uint32_t fh[4], fl[4];
            ldsm4(fh, sF,  half * 64 + mj * 16, k0, SX, lane);
            ldsm4(fl, sFl, half * 64 + mj * 16, k0, SX, lane);
            uint32_t b0[2] = {fh[0], fh[2]}, b1[2] = {fh[1], fh[3]};
            uint32_t c0[2] = {fl[0], fl[2]}, c1[2] = {fl[1], fl[3]};
            mma_tf32(acc[2 * mj],     axh, b0);
            mma_tf32(acc[2 * mj],     axl, b0);
            mma_tf32(acc[2 * mj],     axh, c0);
            mma_tf32(acc[2 * mj + 1], axh, b1);
            mma_tf32(acc[2 * mj + 1], axl, b1);
            mma_tf32(acc[2 * mj + 1], axh, c1);
        }
    }
}

__device__ __forceinline__ void store_phi16(uint32_t* dst, int wn, int half,
                                            int g, int cc, const float acc[8][4]) {
    #pragma unroll
    for (int mi = 0; mi < 8; mi++) {
        int col = half * 64 + mi * 8 + 2 * cc;
        uint2 lo, hi;
        lo.x = f2tf32(fmaxf(acc[mi][0], 0.f));
        lo.y = f2tf32(fmaxf(acc[mi][1], 0.f));
        hi.x = f2tf32(fmaxf(acc[mi][2], 0.f));
        hi.y = f2tf32(fmaxf(acc[mi][3], 0.f));
        *(uint2*)&dst[(wn + g) * SW + col]     = lo;
        *(uint2*)&dst[(wn + g + 8) * SW + col] = hi;
    }
}

extern "C" __global__ void __launch_bounds__(NT, 1)
favor_kernel(const float* __restrict__ keys, const float* __restrict__ values,
             const float* __restrict__ queries, const float* __restrict__ features,
             float* __restrict__ outp) {
    extern __shared__ uint32_t smu[];
    uint32_t sb = (uint32_t)__cvta_generic_to_shared(smu);
    const uint32_t sF  = sb;
    const uint32_t sFl = sb + 8704u * 4;
    const uint32_t sX  = sb + OFF_B * 4u;
    const uint32_t sXl = sb + (OFF_B + 8704u) * 4;
    const uint32_t sQt = sb;
    const uint32_t sVt = sb + OFF_B * 4u;
    const uint32_t sKt = sb + OFF_C * 4u;
    uint32_t* Fh  = smu;
    uint32_t* Fl  = smu + 8704;
    uint32_t* Xh  = smu + OFF_B;
    uint32_t* Xl  = smu + OFF_B + 8704;
    uint32_t* Qt  = smu;
    uint32_t* Kt  = smu + OFF_C;
    uint32_t* Vt  = smu + OFF_B;
    uint32_t* Ssl = smu + OFF_C;
    uint32_t* Os  = smu + OFF_B;

    int c = blockIdx.x, h = blockIdx.y, n0 = c * CHUNK;
    int tid = threadIdx.x, warp = tid >> 5, lane = tid & 31;
    int g = lane >> 2, cc = lane & 3;
    int wn = (warp & 7) * 16, half = warp >> 3;
    int fb = h * NCHUNK;
    int s1 = g_flag[fb + c] + 1;

    // ---- fill F split + Xt(keys) split ----
    for (int idx = tid; idx < MM * DD; idx += NT) {
        int m = idx >> 6, d = idx & 63;
        float f = features[idx];
        uint32_t hi = f2tf32(f);
        Fh[m * SX + d] = hi;
        Fl[m * SX + d] = f2tf32(f - __uint_as_float(hi));
    }
    {
        const float* Xg = keys + (h * DD) * NSEQ + n0;
        for (int idx = tid; idx < DD * CHUNK; idx += NT) {
            int d = idx >> 7, n = idx & 127;
            float x = Xg[d * NSEQ + n];
            uint32_t hi = f2tf32(x);
            Xh[n * SX + d] = hi;
            Xl[n * SX + d] = f2tf32(x - __uint_as_float(hi));
        }
    }
    __syncthreads();

    // ---- phiK -> Kt[t][m] ----
    {
        float acc[8][4];
        phi_mma16(sX, sXl, sF, sFl, wn, half, lane, acc);
        store_phi16(Kt, wn, half, g, cc, acc);
    }
    __syncthreads();

    // ---- refill Xt with queries ----
    {
        const float* Xg = queries + (h * DD) * NSEQ + n0;
        for (int idx = tid; idx < DD * CHUNK; idx += NT) {
            int d = idx >> 7, n = idx & 127;
            float x = Xg[d * NSEQ + n];
            uint32_t hi = f2tf32(x);
            Xh[n * SX + d] = hi;
            Xl[n * SX + d] = f2tf32(x - __uint_as_float(hi));
        }
    }
    __syncthreads();

    // ---- phiQ; sync; Qt overlays F; Vt overlays Xt ----
    {
        float acc[8][4];
        phi_mma16(sX, sXl, sF, sFl, wn, half, lane, acc);
        __syncthreads();
        store_phi16(Qt, wn, half, g, cc, acc);
    }
    {
        const uint32_t ONE = f2tf32(1.0f);
        for (int idx = tid; idx < DVV * CHUNK; idx += NT) {
            int v = idx >> 7, t = idx & 127;
            Vt[v * SW + t] = f2tf32(values[(h * DVV + v) * NSEQ + n0 + t]);
        }
        for (int idx = tid; idx < 16 * CHUNK; idx += NT) {   // rows 64..79
            int v = 64 + (idx >> 7), t = idx & 127;
            Vt[v * SW + t] = (v == DVV) ? ONE : 0u;
        }
    }
    __syncthreads();

    // ---- S[m][v], v-tiles split by half (half0: vi 0..5; half1: vi 6..8) ----
    {
        float sa[6][4];
        #pragma unroll
        for (int l = 0; l < 6; l++)
            #pragma unroll
            for (int r = 0; r < 4; r++) sa[l][r] = 0.f;
        int vp0 = half ? 3 : 0, nvp = half ? 2 : 3;
        #pragma unroll 2
        for (int k0 = 0; k0 < CHUNK; k0 += 8) {
            uint32_t af[4];
            af[0] = Kt[(k0 + cc) * SW + wn + g];
            af[1] = Kt[(k0 + cc) * SW + wn + g + 8];
            af[2] = Kt[(k0 + 4 + cc) * SW + wn + g];
            af[3] = Kt[(k0 + 4 + cc) * SW + wn + g + 8];
            #pragma unroll
            for (int p = 0; p < 3; p++) {
                if (p >= nvp) break;
                int vp = vp0 + p;
                uint32_t vv[4];
                ldsm4(vv, sVt, vp * 16, k0, SW, lane);
                uint32_t b0[2] = {vv[0], vv[2]}, b1[2] = {vv[1], vv[3]};
                mma_tf32(sa[2 * p], af, b0);
                if (vp < 4) mma_tf32(sa[2 * p + 1], af, b1);   // skip pad tile 9
            }
        }
        float* Sg = g_S + (long)(fb + c) * (65 * MM);
        int nl = half ? 3 : 6;
        #pragma unroll
        for (int l = 0; l < 6; l++) {
            if (l >= nl) break;
            int vi = half ? (6 + l) : l;
            int v0 = vi * 8 + 2 * cc;
            if (v0 < 65) {
                Sg[v0 * MM + wn + g]     = sa[l][0];
                Sg[v0 * MM + wn + g + 8] = sa[l][2];
            }
            if (v0 + 1 < 65) {
                Sg[(v0 + 1) * MM + wn + g]     = sa[l][1];
                Sg[(v0 + 1) * MM + wn + g + 8] = sa[l][3];
            }
        }
    }
    __threadfence();
    __syncthreads();
    if (tid == 0) atomicAdd(&g_flag[fb + c], 1);

    // ---- A = Q·K^T over m, t-half split; causal mask; frags in regs ----
    bool skipA = (half == 1) && (wn < 64);   // whole t-half masked out
    uint32_t aA[8][4];
    #pragma unroll
    for (int j = 0; j < 8; j++)
        #pragma unroll
        for (int r = 0; r < 4; r++) aA[j][r] = 0u;
    if (!skipA) {
        float acc[8][4];
        #pragma unroll
        for (int j = 0; j < 8; j++)
            #pragma unroll
            for (int r = 0; r < 4; r++) acc[j][r] = 0.f;
        #pragma unroll 2
        for (int k0 = 0; k0 < MM; k0 += 8) {
            uint32_t af[4];
            ldsm4(af, sQt, wn, k0, SW, lane);
            #pragma unroll
            for (int tp = 0; tp < 4; tp++) {
                uint32_t kk[4];
                ldsm4(kk, sKt, half * 64 + tp * 16, k0, SW, lane);
                uint32_t b0[2] = {kk[0], kk[2]}, b1[2] = {kk[1], kk[3]};
                mma_tf32(acc[2 * tp],     af, b0);
                mma_tf32(acc[2 * tp + 1], af, b1);
            }
        }
        int srcA = (g << 2) | (cc >> 1);
        int srcB = srcA + 2;
        bool odd = cc & 1;
        int nlo = wn + g, nhi = wn + g + 8;
        #pragma unroll
        for (int j = 0; j < 8; j++) {
            int t0 = half * 64 + j * 8 + 2 * cc;
            float m0 = (t0     <= nlo) ? acc[j][0] : 0.f;
            float m1 = (t0 + 1 <= nlo) ? acc[j][1] : 0.f;
            float m2 = (t0     <= nhi) ? acc[j][2] : 0.f;
            float m3 = (t0 + 1 <= nhi) ? acc[j][3] : 0.f;
            float x0 = __shfl_sync(0xffffffffu, m0, srcA);
            float x1 = __shfl_sync(0xffffffffu, m1, srcA);
            float x2 = __shfl_sync(0xffffffffu, m2, srcA);
            float x3 = __shfl_sync(0xffffffffu, m3, srcA);
            float y0 = __shfl_sync(0xffffffffu, m0, srcB);
            float y1 = __shfl_sync(0xffffffffu, m1, srcB);
            float y2 = __shfl_sync(0xffffffffu, m2, srcB);
            float y3 = __shfl_sync(0xffffffffu, m3, srcB);
            aA[j][0] = f2tf32(odd ? x1 : x0);
            aA[j][1] = f2tf32(odd ? x3 : x2);
            aA[j][2] = f2tf32(odd ? y1 : y0);
            aA[j][3] = f2tf32(odd ? y3 : y2);
        }
    }

    // ---- wait for prior chunks; accumulate prefix in regs (512-way) ----
    float run[17];
    #pragma unroll
    for (int i = 0; i < 17; i++) run[i] = 0.f;
    if (tid == 0) {
        for (int pc = 0; pc < c; pc++)
            while (ld_acquire(&g_flag[fb + pc]) < s1) __nanosleep(64);
        __threadfence();
    }
    __syncthreads();
    for (int pc = 0; pc < c; pc++) {
        const float* Sg = g_S + (long)(fb + pc) * (65 * MM);
        #pragma unroll
        for (int i = 0; i < 17; i++) {
            int e = tid + NT * i;
            if (e < 65 * MM) run[i] += Sg[e];
        }
    }
    __syncthreads();   // Kt reads (A phase) done -> Ssl overlay safe

    // ---- Ssl[v][m] tf32 over Kt region; pad rows 65..79 ----
    #pragma unroll
    for (int i = 0; i < 17; i++) {
        int e = tid + NT * i;
        if (e < 65 * MM) Ssl[(e >> 7) * SW + (e & 127)] = f2tf32(run[i]);
    }
    for (int idx = tid; idx < 15 * MM; idx += NT) {
        int v = 65 + idx / MM, m = idx & 127;
        Ssl[v * SW + m] = 0u;
    }
    __syncthreads();

    // ---- phase b: split-k across halves. part1 k=t(half), part2 k=m(half) ----
    float accB[9][4];
    #pragma unroll
    for (int vi = 0; vi < 9; vi++)
        #pragma unroll
        for (int r = 0; r < 4; r++) accB[vi][r] = 0.f;

    if (!skipA) {
        #pragma unroll 2
        for (int j = 0; j < 8; j++) {
            int k0 = half * 64 + j * 8;
            #pragma unroll
            for (int vp = 0; vp < 5; vp++) {
                uint32_t vv[4];
                ldsm4(vv, sVt, vp * 16, k0, SW, lane);
                uint32_t b0[2] = {vv[0], vv[2]}, b1[2] = {vv[1], vv[3]};
                mma_tf32(accB[2 * vp], aA[j], b0);
                if (vp < 4) mma_tf32(accB[2 * vp + 1], aA[j], b1);
            }
        }
    }
    #pragma unroll 2
    for (int ks = 0; ks < 8; ks++) {
        int k0 = half * 64 + ks * 8;
        uint32_t qa[4];
        ldsm4(qa, sQt, wn, k0, SW, lane);
        #pragma unroll
        for (int vp = 0; vp < 5; vp++) {
            uint32_t ss[4];
            ldsm4(ss, sKt, vp * 16, k0, SW, lane);
            uint32_t b0[2] = {ss[0], ss[2]}, b1[2] = {ss[1], ss[3]};
            mma_tf32(accB[2 * vp], qa, b0);
            if (vp < 4) mma_tf32(accB[2 * vp + 1], qa, b1);
        }
    }
    __syncthreads();   // Vt/Ssl reads done -> Os staging over region B

    // ---- pairwise reduction: half0 writes partial, half1 adds + divides ----
    if (half == 0) {
        #pragma unroll
        for (int vi = 0; vi < 9; vi++) {
            int v0 = vi * 8 + 2 * cc;
            Os[v0 * SW + wn + g]           = __float_as_uint(accB[vi][0]);
            Os[(v0 + 1) * SW + wn + g]     = __float_as_uint(accB[vi][1]);
            Os[v0 * SW + wn + g + 8]       = __float_as_uint(accB[vi][2]);
            Os[(v0 + 1) * SW + wn + g + 8] = __float_as_uint(accB[vi][3]);
        }
    }
    __syncthreads();
    if (half == 1) {
        #pragma unroll
        for (int vi = 0; vi < 9; vi++) {
            int v0 = vi * 8 + 2 * cc;
            accB[vi][0] += __uint_as_float(Os[v0 * SW + wn + g]);
            accB[vi][1] += __uint_as_float(Os[(v0 + 1) * SW + wn + g]);
            accB[vi][2] += __uint_as_float(Os[v0 * SW + wn + g + 8]);
            accB[vi][3] += __uint_as_float(Os[(v0 + 1) * SW + wn + g + 8]);
        }
        float nlo = __shfl_sync(0xffffffffu, accB[8][0], lane & ~3);
        float nhi = __shfl_sync(0xffffffffu, accB[8][2], lane & ~3);
        float rlo = 1.f / nlo, rhi = 1.f / nhi;
        #pragma unroll
        for (int vi = 0; vi < 8; vi++) {
            int v0 = vi * 8 + 2 * cc;
            Os[v0 * SW + wn + g]           = __float_as_uint(accB[vi][0] * rlo);
            Os[(v0 + 1) * SW + wn + g]     = __float_as_uint(accB[vi][1] * rlo);
            Os[v0 * SW + wn + g + 8]       = __float_as_uint(accB[vi][2] * rhi);
            Os[(v0 + 1) * SW + wn + g + 8] = __float_as_uint(accB[vi][3] * rhi);
        }
    }
    __syncthreads();

    // ---- coalesced global store ----
    for (int idx = tid; idx < DVV * CHUNK; idx += NT) {
        int v = idx >> 7, n = idx & 127;
        outp[(h * DVV + v) * NSEQ + n0 + n] = __uint_as_float(Os[v * SW + n]);
    }
}

static const int SM_BYTES = SM_U32 * 4;   // 206848

extern "C" void kernel_launch(void* const* d_in, const int* in_sizes, int n_in,
                              void* d_out, int out_size) {
    const float* keys     = (const float*)d_in[0];
    const float* values   = (const float*)d_in[1];
    const float* queries  = (const float*)d_in[2];
    const float* features = (const float*)d_in[3];
    float* outp = (float*)d_out;

    cudaFuncSetAttribute(favor_kernel, cudaFuncAttributeMaxDynamicSharedMemorySize, SM_BYTES);
    favor_kernel<<<dim3(NCHUNK, HH), NT, SM_BYTES>>>(keys, values, queries, features, outp);
}

// round 8
// speedup vs baseline: 1.3336x; 1.3336x over previous
#include <cuda_runtime.h>
#include <cstdint>

// FAVOR causal linear attention — R8: R4 base (mma.sync tf32 + ldmatrix),
// single-term phi (no hi/lo compensation) + triangular HMMA skips.
// B=1,H=8,D=64,DV=64,N=2048,M=128. Chunk C=128, grid(16,8)=128 blocks (1 wave).
// NOTE: tcgen05 unavailable (harness compiles via compute_103 PTX target).

#define HH     8
#define DD     64
#define DVV    64
#define NSEQ   2048
#define MM     128
#define CHUNK  128
#define NCHUNK 16
#define SX     68
#define SW     132
#define OFF_B  17408
#define OFF_C  34816
#define SM_U32 51712   // 206848 bytes

__device__ float g_S[HH * NCHUNK * 65 * MM];   // [h][c][v*128+m], v=64 is z
__device__ int   g_flag[HH * NCHUNK];

__device__ __forceinline__ uint32_t f2tf32(float x) {
    uint32_t r;
    asm("cvt.rna.tf32.f32 %0, %1;" : "=r"(r) : "f"(x));
    return r;
}
__device__ __forceinline__ void mma_tf32(float* c, const uint32_t* a, const uint32_t* b) {
    asm volatile(
        "mma.sync.aligned.m16n8k8.row.col.f32.tf32.tf32.f32 "
        "{%0,%1,%2,%3}, {%4,%5,%6,%7}, {%8,%9}, {%0,%1,%2,%3};"
        : "+f"(c[0]), "+f"(c[1]), "+f"(c[2]), "+f"(c[3])
        : "r"(a[0]), "r"(a[1]), "r"(a[2]), "r"(a[3]), "r"(b[0]), "r"(b[1]));
}
__device__ __forceinline__ int ld_acquire(const int* p) {
    int v;
    asm volatile("ld.acquire.gpu.b32 %0, [%1];" : "=r"(v) : "l"(p) : "memory");
    return v;
}
// 16-row x 8-tf32-col fragment via ldmatrix (b16 view). A-frag: r[0..3];
// as two B-frags: {r0,r2} (rows +0..7) and {r1,r3} (rows +8..15).
__device__ __forceinline__ void ldsm4(uint32_t r[4], uint32_t sbase,
                                      int row0, int k0, int stride, int lane) {
    uint32_t addr = sbase +
        (uint32_t)(((row0 + (lane & 7) + (lane & 8)) * stride + k0 + ((lane & 16) >> 2)) * 4);
    asm volatile("ldmatrix.sync.aligned.m8n8.x4.shared.b16 {%0,%1,%2,%3}, [%4];"
                 : "=r"(r[0]), "=r"(r[1]), "=r"(r[2]), "=r"(r[3]) : "r"(addr));
}

// phi = relu(X·F^T) transposed: C[n][m], single-term tf32.
__device__ __forceinline__ void phi_mma(uint32_t sX, uint32_t sF,
                                        int wb, int lane, float acc[16][4]) {
    #pragma unroll
    for (int mi = 0; mi < 16; mi++)
        #pragma unroll
        for (int r = 0; r < 4; r++) acc[mi][r] = 0.f;
    #pragma unroll 2
    for (int k0 = 0; k0 < DD; k0 += 8) {
        uint32_t ax[4];
        ldsm4(ax, sX, wb, k0, SX, lane);
        #pragma unroll
        for (int mj = 0; mj < 8; mj++) {
            uint32_t fh[4];
            ldsm4(fh, sF, mj * 16, k0, SX, lane);
            uint32_t b0[2] = {fh[0], fh[2]}, b1[2] = {fh[1], fh[3]};
            mma_tf32(acc[2 * mj],     ax, b0);
            mma_tf32(acc[2 * mj + 1], ax, b1);
        }
    }
}

__device__ __forceinline__ void store_phi(uint32_t* dst, int wb, int g, int cc,
                                          const float acc[16][4]) {
    #pragma unroll
    for (int mi = 0; mi < 16; mi++) {
        uint2 lo, hi;
        lo.x = f2tf32(fmaxf(acc[mi][0], 0.f));
        lo.y = f2tf32(fmaxf(acc[mi][1], 0.f));
        hi.x = f2tf32(fmaxf(acc[mi][2], 0.f));
        hi.y = f2tf32(fmaxf(acc[mi][3], 0.f));
        *(uint2*)&dst[(wb + g) * SW + mi * 8 + 2 * cc]     = lo;
        *(uint2*)&dst[(wb + g + 8) * SW + mi * 8 + 2 * cc] = hi;
    }
}

extern "C" __global__ void __launch_bounds__(256, 1)
favor_kernel(const float* __restrict__ keys, const float* __restrict__ values,
             const float* __restrict__ queries, const float* __restrict__ features,
             float* __restrict__ outp) {
    extern __shared__ uint32_t smu[];
    uint32_t sb = (uint32_t)__cvta_generic_to_shared(smu);
    const uint32_t sF  = sb;                       // F [128][68] (single plane)
    const uint32_t sX  = sb + OFF_B * 4u;          // X [128][68]
    const uint32_t sQt = sb;                       // Qt overlays F region
    const uint32_t sVt = sb + OFF_B * 4u;          // Vt overlays X region
    const uint32_t sKt = sb + OFF_C * 4u;          // Kt / Ssl
    uint32_t* Fh  = smu;
    uint32_t* Xh  = smu + OFF_B;
    uint32_t* Qt  = smu;
    uint32_t* Kt  = smu + OFF_C;
    uint32_t* Vt  = smu + OFF_B;
    uint32_t* Ssl = smu + OFF_C;
    uint32_t* Os  = smu + OFF_B;

    int c = blockIdx.x, h = blockIdx.y, n0 = c * CHUNK;
    int tid = threadIdx.x, warp = tid >> 5, lane = tid & 31;
    int g = lane >> 2, cc = lane & 3;
    int wb = warp * 16;
    int fb = h * NCHUNK;
    int s1 = g_flag[fb + c] + 1;   // epoch baseline

    // ---- fill F + X(keys), single tf32 plane each ----
    for (int idx = tid; idx < MM * DD; idx += 256) {
        int m = idx >> 6, d = idx & 63;
        Fh[m * SX + d] = f2tf32(features[idx]);
    }
    {
        const float* Xg = keys + (h * DD) * NSEQ + n0;
        for (int idx = tid; idx < DD * CHUNK; idx += 256) {
            int d = idx >> 7, n = idx & 127;
            Xh[n * SX + d] = f2tf32(Xg[d * NSEQ + n]);
        }
    }
    __syncthreads();

    // ---- phiK -> Kt[t][m] ----
    {
        float acc[16][4];
        phi_mma(sX, sF, wb, lane, acc);
        store_phi(Kt, wb, g, cc, acc);
    }
    __syncthreads();

    // ---- refill X with queries ----
    {
        const float* Xg = queries + (h * DD) * NSEQ + n0;
        for (int idx = tid; idx < DD * CHUNK; idx += 256) {
            int d = idx >> 7, n = idx & 127;
            Xh[n * SX + d] = f2tf32(Xg[d * NSEQ + n]);
        }
    }
    __syncthreads();

    // ---- phiQ; sync (F reads done); Qt over F; Vt over X ----
    {
        float acc[16][4];
        phi_mma(sX, sF, wb, lane, acc);
        __syncthreads();
        store_phi(Qt, wb, g, cc, acc);
    }
    {
        const uint32_t ONE = f2tf32(1.0f);
        for (int idx = tid; idx < DVV * CHUNK; idx += 256) {
            int v = idx >> 7, t = idx & 127;
            Vt[v * SW + t] = f2tf32(values[(h * DVV + v) * NSEQ + n0 + t]);
        }
        for (int idx = tid; idx < 16 * CHUNK; idx += 256) {   // rows 64..79
            int v = 64 + (idx >> 7), t = idx & 127;
            Vt[v * SW + t] = (v == DVV) ? ONE : 0u;
        }
    }
    __syncthreads();

    // ---- S[m][v] = sum_t K[m][t] Vaug[t][v] -> g_S [v][m] fp32; release ----
    {
        float sa[9][4];
        #pragma unroll
        for (int vi = 0; vi < 9; vi++)
            #pragma unroll
            for (int r = 0; r < 4; r++) sa[vi][r] = 0.f;
        #pragma unroll 2
        for (int k0 = 0; k0 < CHUNK; k0 += 8) {
            uint32_t af[4];
            af[0] = Kt[(k0 + cc) * SW + wb + g];
            af[1] = Kt[(k0 + cc) * SW + wb + g + 8];
            af[2] = Kt[(k0 + 4 + cc) * SW + wb + g];
            af[3] = Kt[(k0 + 4 + cc) * SW + wb + g + 8];
            #pragma unroll
            for (int vp = 0; vp < 5; vp++) {
                uint32_t vv[4];
                ldsm4(vv, sVt, vp * 16, k0, SW, lane);
                uint32_t b0[2] = {vv[0], vv[2]}, b1[2] = {vv[1], vv[3]};
                mma_tf32(sa[2 * vp], af, b0);
                if (vp < 4) mma_tf32(sa[2 * vp + 1], af, b1);
            }
        }
        float* Sg = g_S + (long)(fb + c) * (65 * MM);
        #pragma unroll
        for (int vi = 0; vi < 9; vi++) {
            int v0 = vi * 8 + 2 * cc;
            if (v0 < 65) {
                Sg[v0 * MM + wb + g]     = sa[vi][0];
                Sg[v0 * MM + wb + g + 8] = sa[vi][2];
            }
            if (v0 + 1 < 65) {
                Sg[(v0 + 1) * MM + wb + g]     = sa[vi][1];
                Sg[(v0 + 1) * MM + wb + g + 8] = sa[vi][3];
            }
        }
    }
    __threadfence();
    __syncthreads();
    if (tid == 0) atomicAdd(&g_flag[fb + c], 1);

    // ---- A = Q·K^T over m, causal; triangular skip (tp <= warp) ----
    uint32_t aA[16][4];
    int timax = 2 * warp + 1;          // highest live t-tile (8-col) index
    {
        float acc[16][4];
        #pragma unroll
        for (int ti = 0; ti < 16; ti++)
            #pragma unroll
            for (int r = 0; r < 4; r++) acc[ti][r] = 0.f;
        #pragma unroll 2
        for (int k0 = 0; k0 < MM; k0 += 8) {
            uint32_t af[4];
            ldsm4(af, sQt, wb, k0, SW, lane);
            #pragma unroll
            for (int tp = 0; tp < 8; tp++) {
                if (tp > warp) break;          // tiles fully above diagonal
                uint32_t kk[4];
                ldsm4(kk, sKt, tp * 16, k0, SW, lane);
                uint32_t b0[2] = {kk[0], kk[2]}, b1[2] = {kk[1], kk[3]};
                mma_tf32(acc[2 * tp],     af, b0);
                mma_tf32(acc[2 * tp + 1], af, b1);
            }
        }
        int srcA = (g << 2) | (cc >> 1);
        int srcB = srcA + 2;
        bool odd = cc & 1;
        int nlo = wb + g, nhi = wb + g + 8;
        #pragma unroll
        for (int ti = 0; ti < 16; ti++) {
            if (ti > timax) break;
            int t0 = ti * 8 + 2 * cc;
            float m0 = (t0     <= nlo) ? acc[ti][0] : 0.f;
            float m1 = (t0 + 1 <= nlo) ? acc[ti][1] : 0.f;
            float m2 = (t0     <= nhi) ? acc[ti][2] : 0.f;
            float m3 = (t0 + 1 <= nhi) ? acc[ti][3] : 0.f;
            float x0 = __shfl_sync(0xffffffffu, m0, srcA);
            float x1 = __shfl_sync(0xffffffffu, m1, srcA);
            float x2 = __shfl_sync(0xffffffffu, m2, srcA);
            float x3 = __shfl_sync(0xffffffffu, m3, srcA);
            float y0 = __shfl_sync(0xffffffffu, m0, srcB);
            float y1 = __shfl_sync(0xffffffffu, m1, srcB);
            float y2 = __shfl_sync(0xffffffffu, m2, srcB);
            float y3 = __shfl_sync(0xffffffffu, m3, srcB);
            aA[ti][0] = f2tf32(odd ? x1 : x0);
            aA[ti][1] = f2tf32(odd ? x3 : x2);
            aA[ti][2] = f2tf32(odd ? y1 : y0);
            aA[ti][3] = f2tf32(odd ? y3 : y2);
        }
    }

    // ---- wait for prior chunks; accumulate prefix in regs ----
    float run[33];
    #pragma unroll
    for (int i = 0; i < 33; i++) run[i] = 0.f;
    if (tid == 0) {
        for (int pc = 0; pc < c; pc++)
            while (ld_acquire(&g_flag[fb + pc]) < s1) __nanosleep(64);
        __threadfence();
    }
    __syncthreads();
    for (int pc = 0; pc < c; pc++) {
        const float* Sg = g_S + (long)(fb + pc) * (65 * MM);
        #pragma unroll
        for (int i = 0; i < 33; i++) {
            int e = tid + 256 * i;
            if (e < 65 * MM) run[i] += Sg[e];
        }
    }
    __syncthreads();   // Kt reads (A phase) done -> Ssl overlay safe

    // ---- Ssl[v][m] tf32 over Kt region; pad rows 65..79 ----
    #pragma unroll
    for (int i = 0; i < 33; i++) {
        int e = tid + 256 * i;
        if (e < 65 * MM) Ssl[(e >> 7) * SW + (e & 127)] = f2tf32(run[i]);
    }
    for (int idx = tid; idx < 15 * MM; idx += 256) {
        int v = 65 + idx / MM, m = idx & 127;
        Ssl[v * SW + m] = 0u;
    }
    __syncthreads();

    // ---- phase b: O[n][72v] = A@Vaug + Q@Ssl; col 64 = normalizer ----
    float accB[9][4];
    #pragma unroll
    for (int vi = 0; vi < 9; vi++)
        #pragma unroll
        for (int r = 0; r < 4; r++) accB[vi][r] = 0.f;
    #pragma unroll 2
    for (int kb = 0; kb < 16; kb++) {            // intra: k = t (skip masked)
        if (kb > timax) break;
        #pragma unroll
        for (int vp = 0; vp < 5; vp++) {
            uint32_t vv[4];
            ldsm4(vv, sVt, vp * 16, kb * 8, SW, lane);
            uint32_t b0[2] = {vv[0], vv[2]}, b1[2] = {vv[1], vv[3]};
            mma_tf32(accB[2 * vp], aA[kb], b0);
            if (vp < 4) mma_tf32(accB[2 * vp + 1], aA[kb], b1);
        }
    }
    #pragma unroll 2
    for (int k0 = 0; k0 < MM; k0 += 8) {         // inter: k = m
        uint32_t qa[4];
        ldsm4(qa, sQt, wb, k0, SW, lane);
        #pragma unroll
        for (int vp = 0; vp < 5; vp++) {
            uint32_t ss[4];
            ldsm4(ss, sKt, vp * 16, k0, SW, lane);
            uint32_t b0[2] = {ss[0], ss[2]}, b1[2] = {ss[1], ss[3]};
            mma_tf32(accB[2 * vp], qa, b0);
            if (vp < 4) mma_tf32(accB[2 * vp + 1], qa, b1);
        }
    }

    // ---- epilogue: divide by norm, stage Os[v][n], coalesced store ----
    {
        float nlo = __shfl_sync(0xffffffffu, accB[8][0], lane & ~3);
        float nhi = __shfl_sync(0xffffffffu, accB[8][2], lane & ~3);
        float rlo = 1.f / nlo, rhi = 1.f / nhi;
        __syncthreads();   // Vt reads done -> Os overlays region B
        #pragma unroll
        for (int vi = 0; vi < 8; vi++) {
            int v = vi * 8 + 2 * cc;
            Os[v * SW + wb + g]           = __float_as_uint(accB[vi][0] * rlo);
            Os[(v + 1) * SW + wb + g]     = __float_as_uint(accB[vi][1] * rlo);
            Os[v * SW + wb + g + 8]       = __float_as_uint(accB[vi][2] * rhi);
            Os[(v + 1) * SW + wb + g + 8] = __float_as_uint(accB[vi][3] * rhi);
        }
        __syncthreads();
        for (int idx = tid; idx < DVV * CHUNK; idx += 256) {
            int v = idx >> 7, n = idx & 127;
            outp[(h * DVV + v) * NSEQ + n0 + n] = __uint_as_float(Os[v * SW + n]);
        }
    }
}

static const int SM_BYTES = SM_U32 * 4;   // 206848

extern "C" void kernel_launch(void* const* d_in, const int* in_sizes, int n_in,
                              void* d_out, int out_size) {
    const float* keys     = (const float*)d_in[0];
    const float* values   = (const float*)d_in[1];
    const float* queries  = (const float*)d_in[2];
    const float* features = (const float*)d_in[3];
    float* outp = (float*)d_out;

    cudaFuncSetAttribute(favor_kernel, cudaFuncAttributeMaxDynamicSharedMemorySize, SM_BYTES);
    favor_kernel<<<dim3(NCHUNK, HH), 256, SM_BYTES>>>(keys, values, queries, features, outp);
}